// round 1
// baseline (speedup 1.0000x reference)
#include <cuda_runtime.h>
#include <math.h>

typedef unsigned long long u64;
#define DEVI __device__ __forceinline__

DEVI u64 pack2(float a, float b){ u64 r; asm("mov.b64 %0, {%1,%2};" : "=l"(r) : "f"(a), "f"(b)); return r; }
DEVI void unpack2(u64 v, float& a, float& b){ asm("mov.b64 {%0,%1}, %2;" : "=f"(a), "=f"(b) : "l"(v)); }
DEVI u64 fma2(u64 a, u64 b, u64 c){ u64 d; asm("fma.rn.f32x2 %0, %1, %2, %3;" : "=l"(d) : "l"(a), "l"(b), "l"(c)); return d; }

static const int BATCH = 4096;

// ---- scratch layout (floats), batch-innermost [C][H][W][B] ----
#define OFF_XT  ((size_t)0)                          // [784][B]
#define OFF_A1  (OFF_XT + (size_t)784*4096)          // [32*196][B]
#define OFF_A2  (OFF_A1 + (size_t)6272*4096)         // [32*49][B]
#define OFF_A3  (OFF_A2 + (size_t)1568*4096)         // [64*16][B]
#define OFF_H1  (OFF_A3 + (size_t)1024*4096)         // [256][B]
#define OFF_MU  (OFF_H1 + (size_t)256*4096)          // [20][B]
#define OFF_LS  (OFF_MU + (size_t)20*4096)           // [20][B]
#define OFF_ZL  (OFF_LS + (size_t)20*4096)           // [20][B]
#define OFF_D1  (OFF_ZL + (size_t)20*4096)           // [256][B]
#define OFF_D2  (OFF_D1 + (size_t)256*4096)          // [1024][B]
#define OFF_D3  (OFF_D2 + (size_t)1024*4096)         // [32*49][B]
#define OFF_D4  (OFF_D3 + (size_t)1568*4096)         // [32*196][B]
#define OFF_YT  (OFF_D4 + (size_t)6272*4096)         // [784][B]
#define SCRATCH_TOTAL (OFF_YT + (size_t)784*4096)

__device__ __align__(256) float g_scratch[SCRATCH_TOTAL];

// ---------------- generic transpose [R][C] -> [C][R] ----------------
__global__ void transpose_k(const float* __restrict__ in, float* __restrict__ out, int R, int C){
    __shared__ float t[32][33];
    int c = blockIdx.x*32 + threadIdx.x;
    int r = blockIdx.y*32 + threadIdx.y;
    if (r < R && c < C) t[threadIdx.y][threadIdx.x] = in[(size_t)r*C + c];
    __syncthreads();
    int c2 = blockIdx.x*32 + threadIdx.y;
    int r2 = blockIdx.y*32 + threadIdx.x;
    if (r2 < R && c2 < C) out[(size_t)c2*R + r2] = t[threadIdx.x][threadIdx.y];
}

// ---------------- unified conv / deconv / fc kernel ----------------
// in : [CIN][HIN][WIN][BATCH]   out : [COUT][HOUT][WOUT][BATCH]
// wt : conv/fc -> [COUT][CIN][K][K] ; deconv -> [CIN][COUT][K][K] (PyTorch ConvT)
// ACT: 0 none, 1 relu, 2 sigmoid
template<int CIN,int COUT,int K,int HIN,int WIN,int HOUT,int WOUT,int STRIDE,int PAD,
         bool DECONV,int OCC,int VEC,int ICC,int ACT>
__global__ void __launch_bounds__(256) convk(
    const float* __restrict__ in, const float* __restrict__ wt,
    const float* __restrict__ bias, float* __restrict__ out)
{
    static_assert(CIN % ICC == 0, "ICC must divide CIN");
    static_assert(COUT % OCC == 0, "OCC must divide COUT");
    constexpr int KK = K*K;
    const int p  = blockIdx.y;
    const int oy = p / WOUT, ox = p % WOUT;
    const int oc0 = blockIdx.z * OCC;
    const int b  = (blockIdx.x * 256 + threadIdx.x) * VEC;

    __shared__ u64 sw[OCC*ICC*KK];   // weight duplicated into both f32 lanes

    u64 acc[OCC][VEC/2];
    #pragma unroll
    for (int j=0;j<OCC;j++){
        float bv = bias[oc0 + j];
        u64 bp = pack2(bv,bv);
        #pragma unroll
        for (int v=0;v<VEC/2;v++) acc[j][v] = bp;
    }

    for (int ic0 = 0; ic0 < CIN; ic0 += ICC){
        __syncthreads();
        for (int i = threadIdx.x; i < OCC*ICC*KK; i += 256){
            int jo = i / (ICC*KK);
            int ic = (i / KK) % ICC;
            int kk = i % KK;
            int g  = DECONV ? (((ic0+ic)*COUT + (oc0+jo))*KK + kk)
                            : (((oc0+jo)*CIN + (ic0+ic))*KK + kk);
            float w = wt[g];
            sw[i] = pack2(w, w);
        }
        __syncthreads();

        #pragma unroll
        for (int ky=0; ky<K; ky++){
            int iy; bool vy;
            if (DECONV){ int t = oy + PAD - ky; vy = (t>=0) && ((t % STRIDE)==0); iy = t / STRIDE; vy = vy && (iy < HIN); }
            else       { iy = oy*STRIDE - PAD + ky; vy = (iy>=0) && (iy < HIN); }
            if (!vy) continue;
            #pragma unroll
            for (int kx=0; kx<K; kx++){
                int ix; bool vx;
                if (DECONV){ int t = ox + PAD - kx; vx = (t>=0) && ((t % STRIDE)==0); ix = t / STRIDE; vx = vx && (ix < WIN); }
                else       { ix = ox*STRIDE - PAD + kx; vx = (ix>=0) && (ix < WIN); }
                if (!vx) continue;
                const int kk = ky*K + kx;
                const float* ipbase = in + ((size_t)(iy*WIN + ix))*BATCH + b;
                #pragma unroll 4
                for (int ic=0; ic<ICC; ic++){
                    const float* ip = ipbase + (size_t)(ic0+ic)*(HIN*WIN)*BATCH;
                    u64 v[VEC/2];
                    if constexpr (VEC == 4){
                        ulonglong2 u = *reinterpret_cast<const ulonglong2*>(ip);
                        v[0] = u.x; v[1] = u.y;
                    } else {
                        v[0] = *reinterpret_cast<const u64*>(ip);
                    }
                    #pragma unroll
                    for (int j=0;j<OCC;j++){
                        u64 wv = sw[(j*ICC + ic)*KK + kk];
                        #pragma unroll
                        for (int h=0; h<VEC/2; h++) acc[j][h] = fma2(v[h], wv, acc[j][h]);
                    }
                }
            }
        }
    }

    #pragma unroll
    for (int j=0;j<OCC;j++){
        float vals[VEC];
        #pragma unroll
        for (int h=0; h<VEC/2; h++){
            float a_, b_; unpack2(acc[j][h], a_, b_);
            vals[2*h] = a_; vals[2*h+1] = b_;
        }
        #pragma unroll
        for (int q=0; q<VEC; q++){
            if (ACT == 1) vals[q] = fmaxf(vals[q], 0.0f);
            else if (ACT == 2) vals[q] = 1.0f / (1.0f + expf(-vals[q]));
        }
        float* op = out + ((size_t)((oc0+j)*(HOUT*WOUT) + p))*BATCH + b;
        if constexpr (VEC == 4) *reinterpret_cast<float4*>(op) = make_float4(vals[0],vals[1],vals[2],vals[3]);
        else                    *reinterpret_cast<float2*>(op) = make_float2(vals[0],vals[1]);
    }
}

// ---------------- latent: 100-step KLD gradient-ascent + reparameterize ----------------
// mu, ls, zl are [20][B]; eps / outMu / outLv are [B][20]
__global__ void latent_k(const float* __restrict__ mu, const float* __restrict__ ls,
                         const float* __restrict__ eps, float* __restrict__ zl,
                         float* __restrict__ outMu, float* __restrict__ outLv)
{
    int i = blockIdx.x*256 + threadIdx.x;
    if (i >= 20*BATCH) return;
    int l = i / BATCH, b = i % BATCH;
    float m = mu[i];
    float s = ls[i];
    outMu[(size_t)b*20 + l] = m;
    outLv[(size_t)b*20 + l] = s;
    float mr = m, sr = s;
    #pragma unroll 4
    for (int k=0;k<100;k++){
        mr = mr + 0.1f*mr;
        sr = sr + 0.05f*(expf(sr) - 1.0f);
    }
    zl[i] = eps[(size_t)b*20 + l] * expf(0.5f*sr) + mr;
}

extern "C" void kernel_launch(void* const* d_in, const int* in_sizes, int n_in,
                              void* d_out, int out_size)
{
    const float* x    = (const float*)d_in[0];
    const float* eps  = (const float*)d_in[1];
    const float* w_c1 = (const float*)d_in[2];  const float* b_c1 = (const float*)d_in[3];
    const float* w_c2 = (const float*)d_in[4];  const float* b_c2 = (const float*)d_in[5];
    const float* w_c3 = (const float*)d_in[6];  const float* b_c3 = (const float*)d_in[7];
    const float* w_fc1= (const float*)d_in[8];  const float* b_fc1= (const float*)d_in[9];
    const float* w_mu = (const float*)d_in[10]; const float* b_mu = (const float*)d_in[11];
    const float* w_ls = (const float*)d_in[12]; const float* b_ls = (const float*)d_in[13];
    const float* w_fc2= (const float*)d_in[14]; const float* b_fc2= (const float*)d_in[15];
    const float* w_fc3= (const float*)d_in[16]; const float* b_fc3= (const float*)d_in[17];
    const float* w_d1 = (const float*)d_in[18]; const float* b_d1 = (const float*)d_in[19];
    const float* w_d2 = (const float*)d_in[20]; const float* b_d2 = (const float*)d_in[21];
    const float* w_d3 = (const float*)d_in[22]; const float* b_d3 = (const float*)d_in[23];
    float* out = (float*)d_out;

    float* S = nullptr;
    cudaGetSymbolAddress((void**)&S, g_scratch);

    float* xT = S + OFF_XT;
    float* a1 = S + OFF_A1;
    float* a2 = S + OFF_A2;
    float* a3 = S + OFF_A3;
    float* h1 = S + OFF_H1;
    float* muB= S + OFF_MU;
    float* lsB= S + OFF_LS;
    float* zl = S + OFF_ZL;
    float* d1h= S + OFF_D1;
    float* d2h= S + OFF_D2;
    float* d3 = S + OFF_D3;
    float* d4 = S + OFF_D4;
    float* yT = S + OFF_YT;

    float* outMu = out + (size_t)BATCH*784;
    float* outLv = outMu + (size_t)BATCH*20;

    dim3 tb(32,32);
    // x [B][784] -> xT [784][B]
    transpose_k<<<dim3(25,128), tb>>>(x, xT, 4096, 784);

    // encoder
    convk<1,  32, 4, 28,28, 14,14, 2,1, false, 16,4, 1,  1><<<dim3(4,196,2), 256>>>(xT,  w_c1, b_c1, a1);
    convk<32, 32, 4, 14,14, 7, 7,  2,1, false, 8, 4, 32, 1><<<dim3(4,49, 4), 256>>>(a1,  w_c2, b_c2, a2);
    convk<32, 64, 3, 7, 7,  4, 4,  2,1, false, 8, 4, 32, 1><<<dim3(4,16, 8), 256>>>(a2,  w_c3, b_c3, a3);
    convk<1024,256,1, 1,1,  1, 1,  1,0, false, 16,2, 256,1><<<dim3(8,1, 16), 256>>>(a3,  w_fc1,b_fc1,h1);
    convk<256, 20, 1, 1,1,  1, 1,  1,0, false, 4, 2, 256,0><<<dim3(8,1, 5 ), 256>>>(h1,  w_mu, b_mu, muB);
    convk<256, 20, 1, 1,1,  1, 1,  1,0, false, 4, 2, 256,0><<<dim3(8,1, 5 ), 256>>>(h1,  w_ls, b_ls, lsB);

    // reversal + reparameterize (+ write mu/logvar outputs)
    latent_k<<<(20*BATCH + 255)/256, 256>>>(muB, lsB, eps, zl, outMu, outLv);

    // decoder
    convk<20, 256, 1, 1,1,  1, 1,  1,0, false, 8, 2, 20, 1><<<dim3(8,1, 32), 256>>>(zl,  w_fc2,b_fc2,d1h);
    convk<256,1024,1, 1,1,  1, 1,  1,0, false, 16,2, 256,1><<<dim3(8,1, 64), 256>>>(d1h, w_fc3,b_fc3,d2h);
    convk<64, 32, 3, 4, 4,  7, 7,  2,1, true,  8, 4, 64, 1><<<dim3(4,49, 4), 256>>>(d2h, w_d1, b_d1, d3);
    convk<32, 32, 4, 7, 7,  14,14, 2,1, true,  8, 4, 32, 1><<<dim3(4,196,4), 256>>>(d3,  w_d2, b_d2, d4);
    convk<32, 1,  4, 14,14, 28,28, 2,1, true,  1, 4, 32, 2><<<dim3(4,784,1), 256>>>(d4,  w_d3, b_d3, yT);

    // yT [784][B] -> x_hat [B][784]
    transpose_k<<<dim3(128,25), tb>>>(yT, out, 784, 4096);
}

// round 2
// speedup vs baseline: 1.0535x; 1.0535x over previous
#include <cuda_runtime.h>
#include <math.h>

typedef unsigned long long u64;
#define DEVI __device__ __forceinline__

DEVI u64 pack2(float a, float b){ u64 r; asm("mov.b64 %0, {%1,%2};" : "=l"(r) : "f"(a), "f"(b)); return r; }
DEVI void unpack2(u64 v, float& a, float& b){ asm("mov.b64 {%0,%1}, %2;" : "=f"(a), "=f"(b) : "l"(v)); }
DEVI u64 fma2(u64 a, u64 b, u64 c){ u64 d; asm("fma.rn.f32x2 %0, %1, %2, %3;" : "=l"(d) : "l"(a), "l"(b), "l"(c)); return d; }

static const int BATCH = 4096;

// ---- scratch layout (floats), batch-innermost [C][H][W][B] ----
#define OFF_XT  ((size_t)0)                          // [784][B]
#define OFF_A1  (OFF_XT + (size_t)784*4096)          // [32*196][B]
#define OFF_A2  (OFF_A1 + (size_t)6272*4096)         // [32*49][B]
#define OFF_A3  (OFF_A2 + (size_t)1568*4096)         // [64*16][B]
#define OFF_H1  (OFF_A3 + (size_t)1024*4096)         // [256][B]
#define OFF_MU  (OFF_H1 + (size_t)256*4096)          // [20][B]
#define OFF_LS  (OFF_MU + (size_t)20*4096)           // [20][B]
#define OFF_ZL  (OFF_LS + (size_t)20*4096)           // [20][B]
#define OFF_D1  (OFF_ZL + (size_t)20*4096)           // [256][B]
#define OFF_D2  (OFF_D1 + (size_t)256*4096)          // [1024][B]
#define OFF_D3  (OFF_D2 + (size_t)1024*4096)         // [32*49][B]
#define OFF_D4  (OFF_D3 + (size_t)1568*4096)         // [32*196][B]
#define OFF_YT  (OFF_D4 + (size_t)6272*4096)         // [784][B]
#define OFF_FCP (OFF_YT + (size_t)784*4096)          // [4][256][B] fc1 split-K partials
#define SCRATCH_TOTAL (OFF_FCP + (size_t)4*256*4096)

__device__ __align__(256) float g_scratch[SCRATCH_TOTAL];

// ---------------- generic transpose [R][C] -> [C][R] ----------------
__global__ void transpose_k(const float* __restrict__ in, float* __restrict__ out, int R, int C){
    __shared__ float t[32][33];
    int c = blockIdx.x*32 + threadIdx.x;
    int r = blockIdx.y*32 + threadIdx.y;
    if (r < R && c < C) t[threadIdx.y][threadIdx.x] = in[(size_t)r*C + c];
    __syncthreads();
    int c2 = blockIdx.x*32 + threadIdx.y;
    int r2 = blockIdx.y*32 + threadIdx.x;
    if (r2 < R && c2 < C) out[(size_t)c2*R + r2] = t[threadIdx.x][threadIdx.y];
}

// ---------------- unified conv / deconv / fc kernel ----------------
// in : [CIN][HIN][WIN][BATCH]   out : [COUT][HOUT][WOUT][BATCH]
// wt : conv/fc -> [COUT][CIN][K][K] ; deconv -> [CIN][COUT][K][K] (PyTorch ConvT)
// ACT: 0 none, 1 relu, 2 sigmoid.  KS: split-K factor (KS>1 -> partial, no bias/act)
// VEC must be 4.  smem weights laid out [ic][kk][oc] as duplicated f32 pairs.
template<int CIN,int COUT,int K,int HIN,int WIN,int HOUT,int WOUT,int STRIDE,int PAD,
         bool DECONV,int OCC,int VEC,int ICC,int ACT,int KS>
__global__ void __launch_bounds__(256,2) convk(
    const float* __restrict__ in, const float* __restrict__ wt,
    const float* __restrict__ bias, float* __restrict__ out)
{
    static_assert(VEC == 4, "VEC must be 4");
    static_assert((CIN/KS) % ICC == 0, "ICC must divide CIN/KS");
    static_assert(COUT % OCC == 0, "OCC must divide COUT");
    static_assert(OCC % 2 == 0, "OCC even");
    constexpr int KK = K*K;
    constexpr int CINP = CIN/KS;
    const int p  = blockIdx.y;
    const int oy = p / WOUT, ox = p % WOUT;
    const int ks  = blockIdx.z % KS;
    const int oc0 = (blockIdx.z / KS) * OCC;
    const int b  = (blockIdx.x * 256 + threadIdx.x) * VEC;
    if (KS > 1) out += (size_t)ks * COUT * HOUT * WOUT * BATCH;

    __shared__ __align__(16) u64 sw[OCC*ICC*KK];   // [ic][kk][oc], dup pairs

    u64 acc[OCC][2];
    #pragma unroll
    for (int j=0;j<OCC;j++){
        u64 bp;
        if (KS == 1){ float bv = bias[oc0 + j]; bp = pack2(bv,bv); }
        else bp = 0ull;
        acc[j][0] = bp; acc[j][1] = bp;
    }

    for (int ic0 = ks*CINP; ic0 < (ks+1)*CINP; ic0 += ICC){
        __syncthreads();
        for (int i = threadIdx.x; i < OCC*ICC*KK; i += 256){
            int j  = i % OCC;
            int rem= i / OCC;
            int kk = rem % KK;
            int ic = rem / KK;
            int g  = DECONV ? (((ic0+ic)*COUT + (oc0+j))*KK + kk)
                            : (((oc0+j)*CIN + (ic0+ic))*KK + kk);
            float w = wt[g];
            sw[i] = pack2(w, w);
        }
        __syncthreads();

        #pragma unroll
        for (int ky=0; ky<K; ky++){
            int iy; bool vy;
            if (DECONV){ int t = oy + PAD - ky; vy = (t>=0) && ((t % STRIDE)==0); iy = t / STRIDE; vy = vy && (iy < HIN); }
            else       { iy = oy*STRIDE - PAD + ky; vy = (iy>=0) && (iy < HIN); }
            if (!vy) continue;
            #pragma unroll
            for (int kx=0; kx<K; kx++){
                int ix; bool vx;
                if (DECONV){ int t = ox + PAD - kx; vx = (t>=0) && ((t % STRIDE)==0); ix = t / STRIDE; vx = vx && (ix < WIN); }
                else       { ix = ox*STRIDE - PAD + kx; vx = (ix>=0) && (ix < WIN); }
                if (!vx) continue;
                const int kk = ky*K + kx;
                const float* ipbase = in + ((size_t)(iy*WIN + ix))*BATCH + b;
                #pragma unroll 2
                for (int ic=0; ic<ICC; ic++){
                    const float* ip = ipbase + (size_t)(ic0+ic)*(HIN*WIN)*BATCH;
                    ulonglong2 u = *reinterpret_cast<const ulonglong2*>(ip);
                    u64 v0 = u.x, v1 = u.y;
                    const u64* swb = &sw[(ic*KK + kk)*OCC];
                    #pragma unroll
                    for (int jj=0; jj<OCC/2; jj++){
                        ulonglong2 w2 = *reinterpret_cast<const ulonglong2*>(swb + 2*jj);
                        acc[2*jj  ][0] = fma2(v0, w2.x, acc[2*jj  ][0]);
                        acc[2*jj  ][1] = fma2(v1, w2.x, acc[2*jj  ][1]);
                        acc[2*jj+1][0] = fma2(v0, w2.y, acc[2*jj+1][0]);
                        acc[2*jj+1][1] = fma2(v1, w2.y, acc[2*jj+1][1]);
                    }
                }
            }
        }
    }

    #pragma unroll
    for (int j=0;j<OCC;j++){
        float vals[4];
        unpack2(acc[j][0], vals[0], vals[1]);
        unpack2(acc[j][1], vals[2], vals[3]);
        #pragma unroll
        for (int q=0; q<4; q++){
            if (ACT == 1) vals[q] = fmaxf(vals[q], 0.0f);
            else if (ACT == 2) vals[q] = 1.0f / (1.0f + expf(-vals[q]));
        }
        float* op = out + ((size_t)((oc0+j)*(HOUT*WOUT) + p))*BATCH + b;
        *reinterpret_cast<float4*>(op) = make_float4(vals[0],vals[1],vals[2],vals[3]);
    }
}

// ---------------- fc1 split-K reduce: h1 = relu(sum_ks part + bias) ----------------
__global__ void fc1red_k(const float* __restrict__ part, const float* __restrict__ bias,
                         float* __restrict__ out)
{
    int i = blockIdx.x*256 + threadIdx.x;        // over 256*4096/4 float4s
    int i4 = i*4;
    if (i4 >= 256*4096) return;
    int j = i4 >> 12;                            // / 4096
    const float4* p = reinterpret_cast<const float4*>(part);
    const int slab = 256*4096/4;
    float4 a = p[i], b2 = p[i+slab], c = p[i+2*slab], d = p[i+3*slab];
    float bv = bias[j];
    float4 r;
    r.x = fmaxf(a.x+b2.x+c.x+d.x+bv, 0.0f);
    r.y = fmaxf(a.y+b2.y+c.y+d.y+bv, 0.0f);
    r.z = fmaxf(a.z+b2.z+c.z+d.z+bv, 0.0f);
    r.w = fmaxf(a.w+b2.w+c.w+d.w+bv, 0.0f);
    reinterpret_cast<float4*>(out)[i] = r;
}

// ---------------- specialized deconv3: 32->1, k=4, s=2, p=1, 14x14 -> 28x28, sigmoid ----
// block: one output row oy, 4 consecutive ox (tile t), 1024 batch lanes.
// x-mapping for ox=4t+p: uses ix in {2t-1, 2t, 2t+1, 2t+2} = L0..L3.
__global__ void __launch_bounds__(256,4) deconv3_k(
    const float* __restrict__ in,   // [32][14][14][B]
    const float* __restrict__ wt,   // [32][1][4][4]
    const float* __restrict__ bias, float* __restrict__ out) // [784][B]
{
    __shared__ __align__(16) u64 sw[32*16];
    for (int i = threadIdx.x; i < 512; i += 256){ float w = wt[i]; sw[i] = pack2(w,w); }
    __syncthreads();

    const int t  = blockIdx.y % 7;
    const int oy = blockIdx.y / 7;
    const int b  = (blockIdx.x*256 + threadIdx.x) * 4;

    float bv = bias[0];
    u64 bp = pack2(bv,bv);
    u64 acc[4][2];
    #pragma unroll
    for (int p2=0;p2<4;p2++){ acc[p2][0]=bp; acc[p2][1]=bp; }

    const bool v0 = (2*t-1) >= 0;
    const bool v3 = (2*t+2) < 14;
    const int ky0 = (oy + 1) & 1;

    #pragma unroll
    for (int kyi=0; kyi<2; kyi++){
        const int ky = ky0 + 2*kyi;
        const int iy = (oy + 1 - ky) >> 1;
        if (iy < 0 || iy >= 14) continue;
        for (int ic=0; ic<32; ic++){
            const float* ipb = in + ((size_t)(ic*196 + iy*14 + 2*t - 1))*BATCH + b;
            u64 L[4][2];
            #pragma unroll
            for (int k=0;k<4;k++){
                bool valid = (k==0) ? v0 : (k==3 ? v3 : true);
                if (valid){
                    ulonglong2 u = *reinterpret_cast<const ulonglong2*>(ipb + (size_t)k*BATCH);
                    L[k][0]=u.x; L[k][1]=u.y;
                } else { L[k][0]=0; L[k][1]=0; }
            }
            const u64* wb = &sw[ic*16 + ky*4];
            u64 w0=wb[0], w1=wb[1], w2=wb[2], w3=wb[3];
            #pragma unroll
            for (int h=0;h<2;h++){
                acc[0][h] = fma2(L[1][h], w1, acc[0][h]);
                acc[0][h] = fma2(L[0][h], w3, acc[0][h]);
                acc[1][h] = fma2(L[2][h], w0, acc[1][h]);
                acc[1][h] = fma2(L[1][h], w2, acc[1][h]);
                acc[2][h] = fma2(L[2][h], w1, acc[2][h]);
                acc[2][h] = fma2(L[1][h], w3, acc[2][h]);
                acc[3][h] = fma2(L[3][h], w0, acc[3][h]);
                acc[3][h] = fma2(L[2][h], w2, acc[3][h]);
            }
        }
    }

    #pragma unroll
    for (int p2=0;p2<4;p2++){
        float vals[4];
        unpack2(acc[p2][0], vals[0], vals[1]);
        unpack2(acc[p2][1], vals[2], vals[3]);
        #pragma unroll
        for (int q=0;q<4;q++) vals[q] = 1.0f / (1.0f + expf(-vals[q]));
        float* op = out + ((size_t)(oy*28 + 4*t + p2))*BATCH + b;
        *reinterpret_cast<float4*>(op) = make_float4(vals[0],vals[1],vals[2],vals[3]);
    }
}

// ---------------- latent: 100-step KLD gradient-ascent + reparameterize ----------------
__global__ void latent_k(const float* __restrict__ mu, const float* __restrict__ ls,
                         const float* __restrict__ eps, float* __restrict__ zl,
                         float* __restrict__ outMu, float* __restrict__ outLv)
{
    int i = blockIdx.x*256 + threadIdx.x;
    if (i >= 20*BATCH) return;
    int l = i / BATCH, b = i % BATCH;
    float m = mu[i];
    float s = ls[i];
    outMu[(size_t)b*20 + l] = m;
    outLv[(size_t)b*20 + l] = s;
    float mr = m, sr = s;
    #pragma unroll 4
    for (int k=0;k<100;k++){
        mr = mr + 0.1f*mr;
        sr = sr + 0.05f*(expf(sr) - 1.0f);
    }
    zl[i] = eps[(size_t)b*20 + l] * expf(0.5f*sr) + mr;
}

extern "C" void kernel_launch(void* const* d_in, const int* in_sizes, int n_in,
                              void* d_out, int out_size)
{
    const float* x    = (const float*)d_in[0];
    const float* eps  = (const float*)d_in[1];
    const float* w_c1 = (const float*)d_in[2];  const float* b_c1 = (const float*)d_in[3];
    const float* w_c2 = (const float*)d_in[4];  const float* b_c2 = (const float*)d_in[5];
    const float* w_c3 = (const float*)d_in[6];  const float* b_c3 = (const float*)d_in[7];
    const float* w_fc1= (const float*)d_in[8];  const float* b_fc1= (const float*)d_in[9];
    const float* w_mu = (const float*)d_in[10]; const float* b_mu = (const float*)d_in[11];
    const float* w_ls = (const float*)d_in[12]; const float* b_ls = (const float*)d_in[13];
    const float* w_fc2= (const float*)d_in[14]; const float* b_fc2= (const float*)d_in[15];
    const float* w_fc3= (const float*)d_in[16]; const float* b_fc3= (const float*)d_in[17];
    const float* w_d1 = (const float*)d_in[18]; const float* b_d1 = (const float*)d_in[19];
    const float* w_d2 = (const float*)d_in[20]; const float* b_d2 = (const float*)d_in[21];
    const float* w_d3 = (const float*)d_in[22]; const float* b_d3 = (const float*)d_in[23];
    float* out = (float*)d_out;

    float* S = nullptr;
    cudaGetSymbolAddress((void**)&S, g_scratch);

    float* xT = S + OFF_XT;
    float* a1 = S + OFF_A1;
    float* a2 = S + OFF_A2;
    float* a3 = S + OFF_A3;
    float* h1 = S + OFF_H1;
    float* muB= S + OFF_MU;
    float* lsB= S + OFF_LS;
    float* zl = S + OFF_ZL;
    float* d1h= S + OFF_D1;
    float* d2h= S + OFF_D2;
    float* d3 = S + OFF_D3;
    float* d4 = S + OFF_D4;
    float* yT = S + OFF_YT;
    float* fcp= S + OFF_FCP;

    float* outMu = out + (size_t)BATCH*784;
    float* outLv = outMu + (size_t)BATCH*20;

    dim3 tb(32,32);
    transpose_k<<<dim3(25,128), tb>>>(x, xT, 4096, 784);

    // encoder                                             OCC VEC ICC ACT KS
    convk<1,  32, 4, 28,28, 14,14, 2,1, false, 16,4, 1,  1,1><<<dim3(4,196,2), 256>>>(xT,  w_c1, b_c1, a1);
    convk<32, 32, 4, 14,14, 7, 7,  2,1, false, 16,4, 16, 1,1><<<dim3(4,49, 2), 256>>>(a1,  w_c2, b_c2, a2);
    convk<32, 64, 3, 7, 7,  4, 4,  2,1, false, 16,4, 16, 1,1><<<dim3(4,16, 4), 256>>>(a2,  w_c3, b_c3, a3);
    convk<1024,256,1, 1,1,  1, 1,  1,0, false, 16,4, 256,0,4><<<dim3(4,1, 64), 256>>>(a3,  w_fc1,b_fc1,fcp);
    fc1red_k<<<(256*4096/4 + 255)/256, 256>>>(fcp, b_fc1, h1);
    convk<256, 20, 1, 1,1,  1, 1,  1,0, false, 4, 4, 256,0,1><<<dim3(4,1, 5 ), 256>>>(h1,  w_mu, b_mu, muB);
    convk<256, 20, 1, 1,1,  1, 1,  1,0, false, 4, 4, 256,0,1><<<dim3(4,1, 5 ), 256>>>(h1,  w_ls, b_ls, lsB);

    latent_k<<<(20*BATCH + 255)/256, 256>>>(muB, lsB, eps, zl, outMu, outLv);

    // decoder
    convk<20, 256, 1, 1,1,  1, 1,  1,0, false, 16,4, 20, 1,1><<<dim3(4,1, 16), 256>>>(zl,  w_fc2,b_fc2,d1h);
    convk<256,1024,1, 1,1,  1, 1,  1,0, false, 16,4, 256,1,1><<<dim3(4,1, 64), 256>>>(d1h, w_fc3,b_fc3,d2h);
    convk<64, 32, 3, 4, 4,  7, 7,  2,1, true,  16,4, 16, 1,1><<<dim3(4,49, 2), 256>>>(d2h, w_d1, b_d1, d3);
    convk<32, 32, 4, 7, 7,  14,14, 2,1, true,  16,4, 16, 1,1><<<dim3(4,196,2), 256>>>(d3,  w_d2, b_d2, d4);
    deconv3_k<<<dim3(4,196), 256>>>(d4, w_d3, b_d3, yT);

    transpose_k<<<dim3(128,25), tb>>>(yT, out, 784, 4096);
}

// round 4
// speedup vs baseline: 1.1407x; 1.0828x over previous
#include <cuda_runtime.h>
#include <math.h>

typedef unsigned long long u64;
typedef unsigned int u32;
#define DEVI __device__ __forceinline__

DEVI u64 pack2(float a, float b){ u64 r; asm("mov.b64 %0, {%1,%2};" : "=l"(r) : "f"(a), "f"(b)); return r; }
DEVI void unpack2(u64 v, float& a, float& b){ asm("mov.b64 {%0,%1}, %2;" : "=f"(a), "=f"(b) : "l"(v)); }
DEVI u64 fma2(u64 a, u64 b, u64 c){ u64 d; asm("fma.rn.f32x2 %0, %1, %2, %3;" : "=l"(d) : "l"(a), "l"(b), "l"(c)); return d; }
DEVI u32 cvt_tf32(float f){ u32 r; asm("cvt.rna.tf32.f32 %0, %1;" : "=r"(r) : "f"(f)); return r; }

static const int BATCH = 4096;

// ---- scratch layout (floats), batch-innermost [C][H][W][B] unless noted ----
#define OFF_XT  ((size_t)0)                          // [784][B]
#define OFF_A1  (OFF_XT + (size_t)784*4096)          // [32*196][B]
#define OFF_A2  (OFF_A1 + (size_t)6272*4096)         // [32*49][B]
#define OFF_A3  (OFF_A2 + (size_t)1568*4096)         // [64*16][B]
#define OFF_H1  (OFF_A3 + (size_t)1024*4096)         // [256][B]
#define OFF_MU  (OFF_H1 + (size_t)256*4096)          // [20][B]
#define OFF_LS  (OFF_MU + (size_t)20*4096)           // [20][B]
#define OFF_ZL  (OFF_LS + (size_t)20*4096)           // [20][B]
#define OFF_D1  (OFF_ZL + (size_t)20*4096)           // [256][B]
#define OFF_D2  (OFF_D1 + (size_t)256*4096)          // [1024][B]
#define OFF_D3  (OFF_D2 + (size_t)1024*4096)         // [32*49][B]
#define OFF_D4  (OFF_D3 + (size_t)1568*4096)         // [32*196][B]
#define OFF_YT  (OFF_D4 + (size_t)6272*4096)         // [784][B]
#define OFF_A3T (OFF_YT + (size_t)784*4096)          // [B][1024] batch-major
#define OFF_D1T (OFF_A3T + (size_t)4096*1024)        // [B][256]  batch-major
#define SCRATCH_TOTAL (OFF_D1T + (size_t)4096*256)

__device__ __align__(256) float g_scratch[SCRATCH_TOTAL];

// ---------------- generic transpose [R][C] -> [C][R] ----------------
__global__ void transpose_k(const float* __restrict__ in, float* __restrict__ out, int R, int C){
    __shared__ float t[32][33];
    int c = blockIdx.x*32 + threadIdx.x;
    int r = blockIdx.y*32 + threadIdx.y;
    if (r < R && c < C) t[threadIdx.y][threadIdx.x] = in[(size_t)r*C + c];
    __syncthreads();
    int c2 = blockIdx.x*32 + threadIdx.y;
    int r2 = blockIdx.y*32 + threadIdx.x;
    if (r2 < R && c2 < C) out[(size_t)c2*R + r2] = t[threadIdx.x][threadIdx.y];
}

// ================= mma.sync tf32 GEMM =================
// out[m][b] = relu?(bias[m] + sum_k W[m][k] * Bact[b][k])
// CTA tile: M=64, N=128(batch), K=32. 8 warps as 2(m) x 4(n), warp tile 32x32.
// mma m16n8k8: per warp per k8: 2 A-frag (lds.128) + 4 B-frag (lds.64) + 8 mma.
// smem holds fragment-permuted tiles; tile strides padded (132/66 floats) to
// avoid bank conflicts on the scatter fill.
template<int KTOT, bool RELU, int MTOT>
__global__ void __launch_bounds__(256) gemm_mma(
    const float* __restrict__ Bact, const float* __restrict__ W,
    const float* __restrict__ bias, float* __restrict__ out)
{
    __shared__ __align__(16) float sA[16*132];   // [tm(4)][tk(4)] tiles, 132 floats each
    __shared__ __align__(16) float sB[64*66];    // [tn(16)][tk(4)] tiles, 66 floats each

    const int tid = threadIdx.x;
    const int lane = tid & 31, wid = tid >> 5;
    const int wm = wid & 1, wn = wid >> 1;       // 2 x 4 warps
    const int group = lane >> 2, tig = lane & 3;
    const int m0 = blockIdx.y * 64;
    const int b0 = blockIdx.x * 128;

    float acc[2][4][4];
    #pragma unroll
    for (int i=0;i<2;i++) for (int j=0;j<4;j++) for (int q=0;q<4;q++) acc[i][j][q] = 0.0f;

    for (int kc = 0; kc < KTOT/32; kc++){
        // ---- fill A (weights 64x32) ----
        #pragma unroll
        for (int it=0; it<2; it++){
            int idx = tid + it*256;              // 512 float4s
            int m = idx >> 3, kq = (idx & 7) * 4;
            float4 v = *reinterpret_cast<const float4*>(W + (size_t)(m0+m)*KTOT + kc*32 + kq);
            int tm = m >> 4, row = m & 15;
            float vv[4] = {v.x, v.y, v.z, v.w};
            #pragma unroll
            for (int j=0;j<4;j++){
                int k = kq + j, tk = k >> 3, col = k & 7;
                int lane_s = ((row & 7) << 2) | (col & 3);
                int reg = ((row >> 3) & 1) | ((col >> 2) << 1);
                *reinterpret_cast<u32*>(&sA[(tm*4 + tk)*132 + lane_s*4 + reg]) = cvt_tf32(vv[j]);
            }
        }
        // ---- fill B (activations 128x32, batch-major rows) ----
        #pragma unroll
        for (int it=0; it<4; it++){
            int idx = tid + it*256;              // 1024 float4s
            int n = idx >> 3, kq = (idx & 7) * 4;
            float4 v = *reinterpret_cast<const float4*>(Bact + (size_t)(b0+n)*KTOT + kc*32 + kq);
            int tn = n >> 3, coln = n & 7;
            float vv[4] = {v.x, v.y, v.z, v.w};
            #pragma unroll
            for (int j=0;j<4;j++){
                int k = kq + j, tk = k >> 3, rowk = k & 7;
                int lane_s = (coln << 2) | (rowk & 3);
                int reg = rowk >> 2;
                *reinterpret_cast<u32*>(&sB[(tn*4 + tk)*66 + lane_s*2 + reg]) = cvt_tf32(vv[j]);
            }
        }
        __syncthreads();

        #pragma unroll
        for (int tk=0; tk<4; tk++){
            u32 af[2][4]; u32 bf[4][2];
            #pragma unroll
            for (int i=0;i<2;i++){
                const float4 t4 = *reinterpret_cast<const float4*>(&sA[((wm*2+i)*4 + tk)*132 + lane*4]);
                af[i][0]=__float_as_uint(t4.x); af[i][1]=__float_as_uint(t4.y);
                af[i][2]=__float_as_uint(t4.z); af[i][3]=__float_as_uint(t4.w);
            }
            #pragma unroll
            for (int j=0;j<4;j++){
                const float2 t2 = *reinterpret_cast<const float2*>(&sB[((wn*4+j)*4 + tk)*66 + lane*2]);
                bf[j][0]=__float_as_uint(t2.x); bf[j][1]=__float_as_uint(t2.y);
            }
            #pragma unroll
            for (int i=0;i<2;i++)
                #pragma unroll
                for (int j=0;j<4;j++){
                    asm volatile(
                        "mma.sync.aligned.m16n8k8.row.col.f32.tf32.tf32.f32 "
                        "{%0,%1,%2,%3}, {%4,%5,%6,%7}, {%8,%9}, {%0,%1,%2,%3};"
                        : "+f"(acc[i][j][0]), "+f"(acc[i][j][1]), "+f"(acc[i][j][2]), "+f"(acc[i][j][3])
                        : "r"(af[i][0]), "r"(af[i][1]), "r"(af[i][2]), "r"(af[i][3]),
                          "r"(bf[j][0]), "r"(bf[j][1]));
                }
        }
        __syncthreads();
    }

    // ---- epilogue: bias + optional relu, write [m][b] ----
    #pragma unroll
    for (int i=0;i<2;i++){
        int mA = m0 + wm*32 + i*16 + group;
        int mB = mA + 8;
        float bA = bias[mA], bB = bias[mB];
        #pragma unroll
        for (int j=0;j<4;j++){
            int n = b0 + wn*32 + j*8 + tig*2;
            float r0 = acc[i][j][0] + bA, r1 = acc[i][j][1] + bA;
            float r2 = acc[i][j][2] + bB, r3 = acc[i][j][3] + bB;
            if (RELU){
                r0 = fmaxf(r0,0.0f); r1 = fmaxf(r1,0.0f);
                r2 = fmaxf(r2,0.0f); r3 = fmaxf(r3,0.0f);
            }
            *reinterpret_cast<float2*>(out + (size_t)mA*4096 + n) = make_float2(r0, r1);
            *reinterpret_cast<float2*>(out + (size_t)mB*4096 + n) = make_float2(r2, r3);
        }
    }
}

// ---------------- unified conv / deconv / fc kernel (scalar fp32x2) ----------------
template<int CIN,int COUT,int K,int HIN,int WIN,int HOUT,int WOUT,int STRIDE,int PAD,
         bool DECONV,int OCC,int VEC,int ICC,int ACT,int KS>
__global__ void __launch_bounds__(256) convk(
    const float* __restrict__ in, const float* __restrict__ wt,
    const float* __restrict__ bias, float* __restrict__ out)
{
    static_assert(VEC == 4, "VEC must be 4");
    static_assert((CIN/KS) % ICC == 0, "ICC must divide CIN/KS");
    static_assert(COUT % OCC == 0, "OCC must divide COUT");
    static_assert(OCC % 2 == 0, "OCC even");
    constexpr int KK = K*K;
    constexpr int CINP = CIN/KS;
    const int p  = blockIdx.y;
    const int oy = p / WOUT, ox = p % WOUT;
    const int ks  = blockIdx.z % KS;
    const int oc0 = (blockIdx.z / KS) * OCC;
    const int b  = (blockIdx.x * 256 + threadIdx.x) * VEC;
    if (KS > 1) out += (size_t)ks * COUT * HOUT * WOUT * BATCH;

    __shared__ __align__(16) u64 sw[OCC*ICC*KK];

    u64 acc[OCC][2];
    #pragma unroll
    for (int j=0;j<OCC;j++){
        u64 bp;
        if (KS == 1){ float bv = bias[oc0 + j]; bp = pack2(bv,bv); }
        else bp = 0ull;
        acc[j][0] = bp; acc[j][1] = bp;
    }

    for (int ic0 = ks*CINP; ic0 < (ks+1)*CINP; ic0 += ICC){
        __syncthreads();
        for (int i = threadIdx.x; i < OCC*ICC*KK; i += 256){
            int j  = i % OCC;
            int rem= i / OCC;
            int kk = rem % KK;
            int ic = rem / KK;
            int g  = DECONV ? (((ic0+ic)*COUT + (oc0+j))*KK + kk)
                            : (((oc0+j)*CIN + (ic0+ic))*KK + kk);
            float w = wt[g];
            sw[i] = pack2(w, w);
        }
        __syncthreads();

        #pragma unroll
        for (int ky=0; ky<K; ky++){
            int iy; bool vy;
            if (DECONV){ int t = oy + PAD - ky; vy = (t>=0) && ((t % STRIDE)==0); iy = t / STRIDE; vy = vy && (iy < HIN); }
            else       { iy = oy*STRIDE - PAD + ky; vy = (iy>=0) && (iy < HIN); }
            if (!vy) continue;
            #pragma unroll
            for (int kx=0; kx<K; kx++){
                int ix; bool vx;
                if (DECONV){ int t = ox + PAD - kx; vx = (t>=0) && ((t % STRIDE)==0); ix = t / STRIDE; vx = vx && (ix < WIN); }
                else       { ix = ox*STRIDE - PAD + kx; vx = (ix>=0) && (ix < WIN); }
                if (!vx) continue;
                const int kk = ky*K + kx;
                const float* ipbase = in + ((size_t)(iy*WIN + ix))*BATCH + b;
                #pragma unroll 2
                for (int ic=0; ic<ICC; ic++){
                    const float* ip = ipbase + (size_t)(ic0+ic)*(HIN*WIN)*BATCH;
                    ulonglong2 u = *reinterpret_cast<const ulonglong2*>(ip);
                    u64 v0 = u.x, v1 = u.y;
                    const u64* swb = &sw[(ic*KK + kk)*OCC];
                    #pragma unroll
                    for (int jj=0; jj<OCC/2; jj++){
                        ulonglong2 w2 = *reinterpret_cast<const ulonglong2*>(swb + 2*jj);
                        acc[2*jj  ][0] = fma2(v0, w2.x, acc[2*jj  ][0]);
                        acc[2*jj  ][1] = fma2(v1, w2.x, acc[2*jj  ][1]);
                        acc[2*jj+1][0] = fma2(v0, w2.y, acc[2*jj+1][0]);
                        acc[2*jj+1][1] = fma2(v1, w2.y, acc[2*jj+1][1]);
                    }
                }
            }
        }
    }

    #pragma unroll
    for (int j=0;j<OCC;j++){
        float vals[4];
        unpack2(acc[j][0], vals[0], vals[1]);
        unpack2(acc[j][1], vals[2], vals[3]);
        #pragma unroll
        for (int q=0; q<4; q++){
            if (ACT == 1) vals[q] = fmaxf(vals[q], 0.0f);
            else if (ACT == 2) vals[q] = 1.0f / (1.0f + expf(-vals[q]));
        }
        float* op = out + ((size_t)((oc0+j)*(HOUT*WOUT) + p))*BATCH + b;
        *reinterpret_cast<float4*>(op) = make_float4(vals[0],vals[1],vals[2],vals[3]);
    }
}

// ---------------- specialized deconv3 ----------------
__global__ void __launch_bounds__(256,4) deconv3_k(
    const float* __restrict__ in, const float* __restrict__ wt,
    const float* __restrict__ bias, float* __restrict__ out)
{
    __shared__ __align__(16) u64 sw[32*16];
    for (int i = threadIdx.x; i < 512; i += 256){ float w = wt[i]; sw[i] = pack2(w,w); }
    __syncthreads();

    const int t  = blockIdx.y % 7;
    const int oy = blockIdx.y / 7;
    const int b  = (blockIdx.x*256 + threadIdx.x) * 4;

    float bv = bias[0];
    u64 bp = pack2(bv,bv);
    u64 acc[4][2];
    #pragma unroll
    for (int p2=0;p2<4;p2++){ acc[p2][0]=bp; acc[p2][1]=bp; }

    const bool v0 = (2*t-1) >= 0;
    const bool v3 = (2*t+2) < 14;
    const int ky0 = (oy + 1) & 1;

    #pragma unroll
    for (int kyi=0; kyi<2; kyi++){
        const int ky = ky0 + 2*kyi;
        const int iy = (oy + 1 - ky) >> 1;
        if (iy < 0 || iy >= 14) continue;
        for (int ic=0; ic<32; ic++){
            const float* ipb = in + ((size_t)(ic*196 + iy*14 + 2*t - 1))*BATCH + b;
            u64 L[4][2];
            #pragma unroll
            for (int k=0;k<4;k++){
                bool valid = (k==0) ? v0 : (k==3 ? v3 : true);
                if (valid){
                    ulonglong2 u = *reinterpret_cast<const ulonglong2*>(ipb + (size_t)k*BATCH);
                    L[k][0]=u.x; L[k][1]=u.y;
                } else { L[k][0]=0; L[k][1]=0; }
            }
            const u64* wb = &sw[ic*16 + ky*4];
            u64 w0=wb[0], w1=wb[1], w2=wb[2], w3=wb[3];
            #pragma unroll
            for (int h=0;h<2;h++){
                acc[0][h] = fma2(L[1][h], w1, acc[0][h]);
                acc[0][h] = fma2(L[0][h], w3, acc[0][h]);
                acc[1][h] = fma2(L[2][h], w0, acc[1][h]);
                acc[1][h] = fma2(L[1][h], w2, acc[1][h]);
                acc[2][h] = fma2(L[2][h], w1, acc[2][h]);
                acc[2][h] = fma2(L[1][h], w3, acc[2][h]);
                acc[3][h] = fma2(L[3][h], w0, acc[3][h]);
                acc[3][h] = fma2(L[2][h], w2, acc[3][h]);
            }
        }
    }

    #pragma unroll
    for (int p2=0;p2<4;p2++){
        float vals[4];
        unpack2(acc[p2][0], vals[0], vals[1]);
        unpack2(acc[p2][1], vals[2], vals[3]);
        #pragma unroll
        for (int q=0;q<4;q++) vals[q] = 1.0f / (1.0f + expf(-vals[q]));
        float* op = out + ((size_t)(oy*28 + 4*t + p2))*BATCH + b;
        *reinterpret_cast<float4*>(op) = make_float4(vals[0],vals[1],vals[2],vals[3]);
    }
}

// ---------------- latent ----------------
__global__ void latent_k(const float* __restrict__ mu, const float* __restrict__ ls,
                         const float* __restrict__ eps, float* __restrict__ zl,
                         float* __restrict__ outMu, float* __restrict__ outLv)
{
    int i = blockIdx.x*256 + threadIdx.x;
    if (i >= 20*BATCH) return;
    int l = i / BATCH, b = i % BATCH;
    float m = mu[i];
    float s = ls[i];
    outMu[(size_t)b*20 + l] = m;
    outLv[(size_t)b*20 + l] = s;
    float mr = m, sr = s;
    #pragma unroll 4
    for (int k=0;k<100;k++){
        mr = mr + 0.1f*mr;
        sr = sr + 0.05f*(expf(sr) - 1.0f);
    }
    zl[i] = eps[(size_t)b*20 + l] * expf(0.5f*sr) + mr;
}

extern "C" void kernel_launch(void* const* d_in, const int* in_sizes, int n_in,
                              void* d_out, int out_size)
{
    const float* x    = (const float*)d_in[0];
    const float* eps  = (const float*)d_in[1];
    const float* w_c1 = (const float*)d_in[2];  const float* b_c1 = (const float*)d_in[3];
    const float* w_c2 = (const float*)d_in[4];  const float* b_c2 = (const float*)d_in[5];
    const float* w_c3 = (const float*)d_in[6];  const float* b_c3 = (const float*)d_in[7];
    const float* w_fc1= (const float*)d_in[8];  const float* b_fc1= (const float*)d_in[9];
    const float* w_mu = (const float*)d_in[10]; const float* b_mu = (const float*)d_in[11];
    const float* w_ls = (const float*)d_in[12]; const float* b_ls = (const float*)d_in[13];
    const float* w_fc2= (const float*)d_in[14]; const float* b_fc2= (const float*)d_in[15];
    const float* w_fc3= (const float*)d_in[16]; const float* b_fc3= (const float*)d_in[17];
    const float* w_d1 = (const float*)d_in[18]; const float* b_d1 = (const float*)d_in[19];
    const float* w_d2 = (const float*)d_in[20]; const float* b_d2 = (const float*)d_in[21];
    const float* w_d3 = (const float*)d_in[22]; const float* b_d3 = (const float*)d_in[23];
    float* out = (float*)d_out;

    float* S = nullptr;
    cudaGetSymbolAddress((void**)&S, g_scratch);

    float* xT = S + OFF_XT;
    float* a1 = S + OFF_A1;
    float* a2 = S + OFF_A2;
    float* a3 = S + OFF_A3;
    float* h1 = S + OFF_H1;
    float* muB= S + OFF_MU;
    float* lsB= S + OFF_LS;
    float* zl = S + OFF_ZL;
    float* d1h= S + OFF_D1;
    float* d2h= S + OFF_D2;
    float* d3 = S + OFF_D3;
    float* d4 = S + OFF_D4;
    float* yT = S + OFF_YT;
    float* a3T= S + OFF_A3T;
    float* d1T= S + OFF_D1T;

    float* outMu = out + (size_t)BATCH*784;
    float* outLv = outMu + (size_t)BATCH*20;

    dim3 tb(32,32);
    transpose_k<<<dim3(25,128), tb>>>(x, xT, 4096, 784);

    // encoder                                             OCC VEC ICC ACT KS
    convk<1,  32, 4, 28,28, 14,14, 2,1, false, 16,4, 1,  1,1><<<dim3(4,196,2), 256>>>(xT,  w_c1, b_c1, a1);
    convk<32, 32, 4, 14,14, 7, 7,  2,1, false, 8, 4, 16, 1,1><<<dim3(4,49, 4), 256>>>(a1,  w_c2, b_c2, a2);
    convk<32, 64, 3, 7, 7,  4, 4,  2,1, false, 8, 4, 16, 1,1><<<dim3(4,16, 8), 256>>>(a2,  w_c3, b_c3, a3);

    // fc1 on mma.sync tf32: a3 [1024][B] -> a3T [B][1024]
    transpose_k<<<dim3(128,32), tb>>>(a3, a3T, 1024, 4096);
    gemm_mma<1024,true,256><<<dim3(32,4), 256>>>(a3T, w_fc1, b_fc1, h1);

    convk<256, 20, 1, 1,1,  1, 1,  1,0, false, 4, 4, 256,0,1><<<dim3(4,1, 5 ), 256>>>(h1,  w_mu, b_mu, muB);
    convk<256, 20, 1, 1,1,  1, 1,  1,0, false, 4, 4, 256,0,1><<<dim3(4,1, 5 ), 256>>>(h1,  w_ls, b_ls, lsB);

    latent_k<<<(20*BATCH + 255)/256, 256>>>(muB, lsB, eps, zl, outMu, outLv);

    // decoder
    convk<20, 256, 1, 1,1,  1, 1,  1,0, false, 16,4, 20, 1,1><<<dim3(4,1, 16), 256>>>(zl,  w_fc2,b_fc2,d1h);
    // fc3 on mma.sync tf32: d1h [256][B] -> d1T [B][256]
    transpose_k<<<dim3(128,8), tb>>>(d1h, d1T, 256, 4096);
    gemm_mma<256,true,1024><<<dim3(32,16), 256>>>(d1T, w_fc3, b_fc3, d2h);

    convk<64, 32, 3, 4, 4,  7, 7,  2,1, true,  8, 4, 16, 1,1><<<dim3(4,49, 4), 256>>>(d2h, w_d1, b_d1, d3);
    convk<32, 32, 4, 7, 7,  14,14, 2,1, true,  8, 4, 16, 1,1><<<dim3(4,196,4), 256>>>(d3,  w_d2, b_d2, d4);
    deconv3_k<<<dim3(4,196), 256>>>(d4, w_d3, b_d3, yT);

    transpose_k<<<dim3(128,25), tb>>>(yT, out, 784, 4096);
}